// round 3
// baseline (speedup 1.0000x reference)
#include <cuda_runtime.h>

#define NNODES 100000
#define NEDGES 1600000
#define NREL 4

// Scratch (static __device__ arrays — allocation-free per harness rules).
// All are zero-initialized at module load; every kernel_launch restores the
// all-zero invariant (combines re-zero scratch), so graph replays are safe.
__device__ __align__(16) float g_S1[NREL * NNODES * 16];  // 25.6 MB
__device__ __align__(16) float g_S2[NREL * NNODES * 16];  // 25.6 MB
__device__ __align__(16) float g_S3[NREL * NNODES * 32];  // 51.2 MB
__device__ int   g_cnt[NREL * NNODES];                    // 1.6 MB
__device__ __align__(16) float g_h1[NNODES * 16];
__device__ __align__(16) float g_h2[NNODES * 32];

typedef unsigned long long ull;

// ---------------------------------------------------------------------------
// f32x2 packed-FMA helpers (sm_100+)
// ---------------------------------------------------------------------------
__device__ __forceinline__ void ffma2(ull& acc, ull a, ull b) {
    asm("fma.rn.f32x2 %0, %1, %2, %0;" : "+l"(acc) : "l"(a), "l"(b));
}
__device__ __forceinline__ ull bcast2(float v) {
    ull r;
    unsigned int u = __float_as_uint(v);
    asm("mov.b64 %0, {%1, %1};" : "=l"(r) : "r"(u));
    return r;
}

// ---------------------------------------------------------------------------
// Scatter: S[r, dst, :] += h[src, :] via vectorized L2 reductions.
// One thread per (edge, float4-chunk). Optionally fuses per-(r,dst) counting.
// ---------------------------------------------------------------------------
template <int DIN, bool COUNT>
__global__ void scatter_kernel(const float* __restrict__ h,
                               const int* __restrict__ src,
                               const int* __restrict__ dst,
                               const int* __restrict__ et,
                               float* __restrict__ S,
                               int* __restrict__ cnt, int n, int e) {
    constexpr int CH = DIN / 4;
    int t = blockIdx.x * blockDim.x + threadIdx.x;
    int ed = t / CH;
    int c  = t - ed * CH;
    if (ed >= e) return;
    int s = __ldg(src + ed);
    int d = __ldg(dst + ed);
    int r = __ldg(et + ed);
    const float4 v = *reinterpret_cast<const float4*>(h + (size_t)s * DIN + c * 4);
    float* p = S + ((size_t)r * n + d) * DIN + c * 4;
    asm volatile("red.global.add.v4.f32 [%0], {%1,%2,%3,%4};"
                 :: "l"(p), "f"(v.x), "f"(v.y), "f"(v.z), "f"(v.w)
                 : "memory");
    if (COUNT && c == 0) atomicAdd(cnt + r * n + d, 1);
}

// ---------------------------------------------------------------------------
// Combine: out[i] = bias + x[i]@root + sum_r (S[r,i]/max(cnt,1)) @ W_r
// SPLIT threads per node, each computing DOUT/SPLIT columns in packed f32x2
// registers. Weights staged in smem (broadcast LDS.128). Explicit LDG
// prefetch across the 5 input blocks. Also grid-stride-zeroes another
// layer's scratch (zbuf) and optionally the cnt array (combine3 only).
// ---------------------------------------------------------------------------
template <int DIN, int DOUT, int SPLIT, bool RELU>
__global__ void __launch_bounds__(256)
combine_kernel(const float* __restrict__ xin,
               const float* __restrict__ S,
               const int* __restrict__ cnt,
               const float* __restrict__ W,     // [R, DIN, DOUT]
               const float* __restrict__ root,  // [DIN, DOUT]
               const float* __restrict__ bias,  // [DOUT]
               float* __restrict__ out, int n,
               float4* __restrict__ zbuf, int zcnt4,
               int* __restrict__ cnt_zero) {
    constexpr int COLS = DOUT / SPLIT;       // columns per thread
    constexpr int NPB  = 256 / SPLIT;        // nodes per block
    __shared__ __align__(16) float sw[5 * DIN * DOUT];

    const int tid = threadIdx.x;
    for (int i = tid; i < DIN * DOUT; i += 256) sw[i] = root[i];
    for (int i = tid; i < NREL * DIN * DOUT; i += 256) sw[DIN * DOUT + i] = W[i];

    // Chore: zero another layer's scratch buffer (grid-stride, overlapped)
    const int gid = blockIdx.x * 256 + tid;
    const float4 z4 = make_float4(0.f, 0.f, 0.f, 0.f);
    for (int i = gid; i < zcnt4; i += gridDim.x * 256) zbuf[i] = z4;

    const int node  = blockIdx.x * NPB + tid / SPLIT;
    const int split = tid % SPLIT;
    const bool valid = node < n;

    float inv[NREL];
    if (valid) {
#pragma unroll
        for (int r = 0; r < NREL; r++) {
            int c = __ldg(cnt + r * n + node);
            inv[r] = 1.0f / (float)(c > 1 ? c : 1);
        }
    }
    __syncthreads();  // weights staged; all in-block cnt reads complete

    // Chore: zero cnt (combine3 only). Owner = (node, split) thread; all
    // readers of cnt[split*n+node] are this node's split threads (same block).
    if (cnt_zero != nullptr && valid && split < NREL)
        cnt_zero[split * n + node] = 0;

    if (!valid) return;

    ull acc[COLS / 2];
    const ull* bb = reinterpret_cast<const ull*>(bias + split * COLS);
#pragma unroll
    for (int j = 0; j < COLS / 2; j++) acc[j] = bb[j];

    const float4* bx = reinterpret_cast<const float4*>(xin + (size_t)node * DIN);
    const float4* bs = reinterpret_cast<const float4*>(S + (size_t)node * DIN);
    const size_t rstride4 = (size_t)n * DIN / 4;

    float4 cur = __ldg(bx);
#pragma unroll
    for (int rb = 0; rb < 5; rb++) {
        const float sc = (rb == 0) ? 1.0f : inv[rb - 1];
        const float4* cb = (rb == 0) ? bx : bs + (size_t)(rb - 1) * rstride4;
#pragma unroll
        for (int c4 = 0; c4 < DIN / 4; c4++) {
            float4 nxt;
            if (c4 + 1 < DIN / 4)      nxt = __ldg(cb + c4 + 1);
            else if (rb < 4)           nxt = __ldg(bs + (size_t)rb * rstride4);
            else                       nxt = z4;

            const float vs[4] = {cur.x * sc, cur.y * sc, cur.z * sc, cur.w * sc};
#pragma unroll
            for (int k = 0; k < 4; k++) {
                const ull v2 = bcast2(vs[k]);
                const ulonglong2* w = reinterpret_cast<const ulonglong2*>(
                    sw + (rb * DIN + c4 * 4 + k) * DOUT + split * COLS);
#pragma unroll
                for (int j = 0; j < COLS / 4; j++) {
                    ffma2(acc[2 * j],     v2, w[j].x);
                    ffma2(acc[2 * j + 1], v2, w[j].y);
                }
            }
            cur = nxt;
        }
    }

    float* op = out + (size_t)node * DOUT + split * COLS;
#pragma unroll
    for (int j = 0; j < COLS / 2; j++) {
        float2 f = *reinterpret_cast<float2*>(&acc[j]);
        if (RELU) {
            f.x = fmaxf(f.x, 0.0f);
            f.y = fmaxf(f.y, 0.0f);
        }
        reinterpret_cast<float2*>(op)[j] = f;
    }
}

// ---------------------------------------------------------------------------
// Launcher: (scatter[+count], combine[+zero-chores]) x 3 layers. No memsets.
// ---------------------------------------------------------------------------
extern "C" void kernel_launch(void* const* d_in, const int* in_sizes, int n_in,
                              void* d_out, int out_size) {
    const float* x     = (const float*)d_in[0];
    const int*   ei    = (const int*)d_in[1];   // [2, E]: src then dst
    const int*   et    = (const int*)d_in[2];
    const float* W1    = (const float*)d_in[3];
    const float* root1 = (const float*)d_in[4];
    const float* b1    = (const float*)d_in[5];
    const float* W2    = (const float*)d_in[6];
    const float* root2 = (const float*)d_in[7];
    const float* b2    = (const float*)d_in[8];
    const float* W3    = (const float*)d_in[9];
    const float* root3 = (const float*)d_in[10];
    const float* b3    = (const float*)d_in[11];
    float* out = (float*)d_out;

    const int n = in_sizes[0] / 16;
    const int e = in_sizes[2];
    const int* src = ei;
    const int* dst = ei + e;

    float *pS1, *pS2, *pS3, *ph1, *ph2;
    int* pcnt;
    cudaGetSymbolAddress((void**)&pS1, g_S1);
    cudaGetSymbolAddress((void**)&pS2, g_S2);
    cudaGetSymbolAddress((void**)&pS3, g_S3);
    cudaGetSymbolAddress((void**)&pcnt, g_cnt);
    cudaGetSymbolAddress((void**)&ph1, g_h1);
    cudaGetSymbolAddress((void**)&ph2, g_h2);

    const int TB = 256;
    const int zS1 = NREL * NNODES * 16 / 4;   // float4 counts
    const int zS2 = NREL * NNODES * 16 / 4;
    const int zS3 = NREL * NNODES * 32 / 4;

    // Layer 1: 16 -> 16, relu. Scatter fuses degree count (cnt==0 on entry).
    {
        int tot = e * 4;
        scatter_kernel<16, true><<<(tot + TB - 1) / TB, TB>>>(
            x, src, dst, et, pS1, pcnt, n, e);
        int grid = (n * 2 + 255) / 256;
        combine_kernel<16, 16, 2, true><<<grid, 256>>>(
            x, pS1, pcnt, W1, root1, b1, ph1, n,
            (float4*)pS2, zS2, nullptr);          // zero S2 before scatter2
    }

    // Layer 2: 16 -> 32, relu
    {
        int tot = e * 4;
        scatter_kernel<16, false><<<(tot + TB - 1) / TB, TB>>>(
            ph1, src, dst, et, pS2, pcnt, n, e);
        int grid = (n * 2 + 255) / 256;
        combine_kernel<16, 32, 2, true><<<grid, 256>>>(
            ph1, pS2, pcnt, W2, root2, b2, ph2, n,
            (float4*)pS3, zS3, nullptr);          // zero S3 before scatter3
    }

    // Layer 3: 32 -> 64, no relu
    {
        int tot = e * 8;
        scatter_kernel<32, false><<<(tot + TB - 1) / TB, TB>>>(
            ph2, src, dst, et, pS3, pcnt, n, e);
        int grid = (n * 4 + 255) / 256;
        combine_kernel<32, 64, 4, false><<<grid, 256>>>(
            ph2, pS3, pcnt, W3, root3, b3, out, n,
            (float4*)pS1, zS1, pcnt);             // zero S1 + cnt for next replay
    }
}

// round 4
// speedup vs baseline: 1.4032x; 1.4032x over previous
#include <cuda_runtime.h>

#define NNODES 100000
#define NEDGES 1600000
#define NREL 4

// Scratch (static __device__ arrays — allocation-free per harness rules)
__device__ __align__(16) float g_S1[NREL * NNODES * 16];  // 25.6 MB
__device__ __align__(16) float g_S2[NREL * NNODES * 16];  // 25.6 MB
__device__ __align__(16) float g_S3[NREL * NNODES * 32];  // 51.2 MB
__device__ int   g_cnt[NREL * NNODES];                    // 1.6 MB
__device__ __align__(16) float g_h1[NNODES * 16];
__device__ __align__(16) float g_h2[NNODES * 32];

typedef unsigned long long ull;

// ---------------------------------------------------------------------------
// f32x2 packed-FMA helpers (sm_100+)
// ---------------------------------------------------------------------------
__device__ __forceinline__ void ffma2(ull& acc, ull a, ull b) {
    asm("fma.rn.f32x2 %0, %1, %2, %0;" : "+l"(acc) : "l"(a), "l"(b));
}
__device__ __forceinline__ ull bcast2(float v) {
    ull r;
    unsigned int u = __float_as_uint(v);
    asm("mov.b64 %0, {%1, %1};" : "=l"(r) : "r"(u));
    return r;
}

// ---------------------------------------------------------------------------
// Scatter: S[r, dst, :] += h[src, :] via vectorized L2 reductions.
// One thread per (edge, float4-chunk). Optionally fuses per-(r,dst) counting.
// ---------------------------------------------------------------------------
template <int DIN, bool COUNT>
__global__ void scatter_kernel(const float* __restrict__ h,
                               const int* __restrict__ src,
                               const int* __restrict__ dst,
                               const int* __restrict__ et,
                               float* __restrict__ S,
                               int* __restrict__ cnt, int n, int e) {
    constexpr int CH = DIN / 4;
    int t = blockIdx.x * blockDim.x + threadIdx.x;
    int ed = t / CH;
    int c  = t - ed * CH;
    if (ed >= e) return;
    int s = __ldg(src + ed);
    int d = __ldg(dst + ed);
    int r = __ldg(et + ed);
    const float4 v = *reinterpret_cast<const float4*>(h + (size_t)s * DIN + c * 4);
    float* p = S + ((size_t)r * n + d) * DIN + c * 4;
    asm volatile("red.global.add.v4.f32 [%0], {%1,%2,%3,%4};"
                 :: "l"(p), "f"(v.x), "f"(v.y), "f"(v.z), "f"(v.w)
                 : "memory");
    if (COUNT && c == 0) atomicAdd(cnt + r * n + d, 1);
}

// ---------------------------------------------------------------------------
// Combine: out[i] = bias + x[i]@root + sum_r (S[r,i]/max(cnt,1)) @ W_r
// Register-tiled: each thread computes NT nodes x 8 columns. Weights staged
// in smem, one LDS.128 feeds 2*NT FFMA2 (broadcast, amortized over nodes).
// NT independent accumulator chains give the ILP the serial version lacked.
// ---------------------------------------------------------------------------
template <int DIN, int DOUT, int NT, bool RELU>
__global__ void __launch_bounds__(256)
combine_kernel(const float* __restrict__ xin,
               const float* __restrict__ S,
               const int* __restrict__ cnt,
               const float* __restrict__ W,     // [R, DIN, DOUT]
               const float* __restrict__ root,  // [DIN, DOUT]
               const float* __restrict__ bias,  // [DOUT]
               float* __restrict__ out, int n) {
    constexpr int COLS  = 8;
    constexpr int SPLIT = DOUT / COLS;       // threads per node (cols)
    constexpr int NG    = 256 / SPLIT;       // node-groups per block
    constexpr int NPB   = NG * NT;           // nodes per block

    __shared__ __align__(16) float sw[5 * DIN * DOUT];
    const int tid = threadIdx.x;
    for (int i = tid; i < DIN * DOUT; i += 256) sw[i] = root[i];
    for (int i = tid; i < NREL * DIN * DOUT; i += 256) sw[DIN * DOUT + i] = W[i];

    const int ng = tid / SPLIT;
    const int sp = tid % SPLIT;
    const int nbase = blockIdx.x * NPB + ng;

    int nodev[NT];
    bool valid[NT];
    float inv[NT][NREL];
#pragma unroll
    for (int i = 0; i < NT; i++) {
        nodev[i] = nbase + i * NG;
        valid[i] = nodev[i] < n;
#pragma unroll
        for (int r = 0; r < NREL; r++) {
            int c = valid[i] ? __ldg(cnt + r * n + nodev[i]) : 1;
            inv[i][r] = 1.0f / (float)(c > 1 ? c : 1);
        }
    }
    __syncthreads();

    ull acc[NT][COLS / 2];
    {
        const ull* bb = reinterpret_cast<const ull*>(bias + sp * COLS);
#pragma unroll
        for (int i = 0; i < NT; i++)
#pragma unroll
            for (int j = 0; j < COLS / 2; j++) acc[i][j] = bb[j];
    }

#pragma unroll
    for (int rb = 0; rb < 5; rb++) {
        const float* __restrict__ mbase =
            (rb == 0) ? xin : S + (size_t)(rb - 1) * n * DIN;
#pragma unroll
        for (int c4 = 0; c4 < DIN / 4; c4++) {
            // Gather NT independent input float4s (MLP batch)
            float4 v[NT];
#pragma unroll
            for (int i = 0; i < NT; i++)
                v[i] = valid[i]
                     ? __ldg(reinterpret_cast<const float4*>(
                           mbase + (size_t)nodev[i] * DIN) + c4)
                     : make_float4(0.f, 0.f, 0.f, 0.f);
            float sc[NT];
#pragma unroll
            for (int i = 0; i < NT; i++)
                sc[i] = (rb == 0) ? 1.0f : inv[i][rb - 1];

#pragma unroll
            for (int k = 0; k < 4; k++) {
                const ulonglong2* wp = reinterpret_cast<const ulonglong2*>(
                    sw + (rb * DIN + c4 * 4 + k) * DOUT + sp * COLS);
                const ulonglong2 w0 = wp[0];  // cols 0..3
                const ulonglong2 w1 = wp[1];  // cols 4..7
#pragma unroll
                for (int i = 0; i < NT; i++) {
                    const float vk = (k == 0) ? v[i].x : (k == 1) ? v[i].y
                                   : (k == 2) ? v[i].z : v[i].w;
                    const ull v2 = bcast2(vk * sc[i]);
                    ffma2(acc[i][0], v2, w0.x);
                    ffma2(acc[i][1], v2, w0.y);
                    ffma2(acc[i][2], v2, w1.x);
                    ffma2(acc[i][3], v2, w1.y);
                }
            }
        }
    }

#pragma unroll
    for (int i = 0; i < NT; i++) {
        if (!valid[i]) continue;
        float* op = out + (size_t)nodev[i] * DOUT + sp * COLS;
#pragma unroll
        for (int j = 0; j < COLS / 2; j++) {
            float2 f = *reinterpret_cast<float2*>(&acc[i][j]);
            if (RELU) {
                f.x = fmaxf(f.x, 0.0f);
                f.y = fmaxf(f.y, 0.0f);
            }
            reinterpret_cast<float2*>(op)[j] = f;
        }
    }
}

// ---------------------------------------------------------------------------
// Launcher: memsets -> (scatter[+count], combine) x 3 layers
// ---------------------------------------------------------------------------
extern "C" void kernel_launch(void* const* d_in, const int* in_sizes, int n_in,
                              void* d_out, int out_size) {
    const float* x     = (const float*)d_in[0];
    const int*   ei    = (const int*)d_in[1];   // [2, E]: src then dst
    const int*   et    = (const int*)d_in[2];
    const float* W1    = (const float*)d_in[3];
    const float* root1 = (const float*)d_in[4];
    const float* b1    = (const float*)d_in[5];
    const float* W2    = (const float*)d_in[6];
    const float* root2 = (const float*)d_in[7];
    const float* b2    = (const float*)d_in[8];
    const float* W3    = (const float*)d_in[9];
    const float* root3 = (const float*)d_in[10];
    const float* b3    = (const float*)d_in[11];
    float* out = (float*)d_out;

    const int n = in_sizes[0] / 16;
    const int e = in_sizes[2];
    const int* src = ei;
    const int* dst = ei + e;

    float *pS1, *pS2, *pS3, *ph1, *ph2;
    int* pcnt;
    cudaGetSymbolAddress((void**)&pS1, g_S1);
    cudaGetSymbolAddress((void**)&pS2, g_S2);
    cudaGetSymbolAddress((void**)&pS3, g_S3);
    cudaGetSymbolAddress((void**)&pcnt, g_cnt);
    cudaGetSymbolAddress((void**)&ph1, g_h1);
    cudaGetSymbolAddress((void**)&ph2, g_h2);

    cudaMemsetAsync(pS1, 0, sizeof(float) * NREL * NNODES * 16);
    cudaMemsetAsync(pS2, 0, sizeof(float) * NREL * NNODES * 16);
    cudaMemsetAsync(pS3, 0, sizeof(float) * NREL * NNODES * 32);
    cudaMemsetAsync(pcnt, 0, sizeof(int) * NREL * NNODES);

    const int TB = 256;

    // Layer 1: 16 -> 16, relu. Scatter fuses degree count.
    {
        int tot = e * 4;
        scatter_kernel<16, true><<<(tot + TB - 1) / TB, TB>>>(
            x, src, dst, et, pS1, pcnt, n, e);
        // NPB = (256/2)*4 = 512
        combine_kernel<16, 16, 4, true><<<(n + 511) / 512, 256>>>(
            x, pS1, pcnt, W1, root1, b1, ph1, n);
    }

    // Layer 2: 16 -> 32, relu
    {
        int tot = e * 4;
        scatter_kernel<16, false><<<(tot + TB - 1) / TB, TB>>>(
            ph1, src, dst, et, pS2, pcnt, n, e);
        // NPB = (256/4)*4 = 256
        combine_kernel<16, 32, 4, true><<<(n + 255) / 256, 256>>>(
            ph1, pS2, pcnt, W2, root2, b2, ph2, n);
    }

    // Layer 3: 32 -> 64, no relu
    {
        int tot = e * 8;
        scatter_kernel<32, false><<<(tot + TB - 1) / TB, TB>>>(
            ph2, src, dst, et, pS3, pcnt, n, e);
        // NPB = (256/8)*4 = 128
        combine_kernel<32, 64, 4, false><<<(n + 127) / 128, 256>>>(
            ph2, pS3, pcnt, W3, root3, b3, out, n);
    }
}